// round 6
// baseline (speedup 1.0000x reference)
#include <cuda_runtime.h>
#include <cuda_bf16.h>
#include <math.h>
#include <stdint.h>

// Problem constants
#define B   64
#define T   2048
#define D   256
#define V   256

typedef unsigned long long ull;

// Scratch in device globals (no allocations allowed)
__device__ float g_EWx[V * D];             // E @ Wx^T
__device__ float g_EG [V * D];             // sigmoid(E @ Wz^T)
__device__ float g_out[(size_t)B * T * D]; // h_t * gate_t (134 MB)

// ---------------------------------------------------------------------------
// f32x2 packed helpers (sm_103a)
// ---------------------------------------------------------------------------
__device__ __forceinline__ ull f2fma(ull a, ull b, ull c) {
    ull d;
    asm("fma.rn.f32x2 %0, %1, %2, %3;" : "=l"(d) : "l"(a), "l"(b), "l"(c));
    return d;
}
__device__ __forceinline__ ull f2add(ull a, ull b) {
    ull d;
    asm("add.rn.f32x2 %0, %1, %2;" : "=l"(d) : "l"(a), "l"(b));
    return d;
}
__device__ __forceinline__ ull f2dup(float x) {
    ull d;
    asm("mov.b64 %0, {%1, %1};" : "=l"(d) : "f"(x));
    return d;
}
__device__ __forceinline__ float f2sum(ull a) {
    float lo, hi;
    asm("mov.b64 {%0, %1}, %2;" : "=f"(lo), "=f"(hi) : "l"(a));
    return lo + hi;
}

// ---------------------------------------------------------------------------
// Kernel 1: precompute token tables as a coalesced dual GEMM (64x64 tiles).
// ---------------------------------------------------------------------------
__global__ __launch_bounds__(256)
void precompute_tables(const float* __restrict__ E,
                       const float* __restrict__ Wx,
                       const float* __restrict__ Wz) {
    __shared__ float As[8][64], Bxs[8][64], Bzs[8][64];
    const int m0 = blockIdx.x << 6;
    const int n0 = blockIdx.y << 6;
    const int tid = threadIdx.x;
    const int lr = tid >> 2;
    const int lc = (tid & 3) << 1;
    const int tm = (tid >> 4) << 2;
    const int tn = (tid & 15) << 2;

    float accx[4][4] = {}, accz[4][4] = {};

    for (int k0 = 0; k0 < D; k0 += 8) {
        float2 a2 = *(const float2*)(E  + ((m0 + lr) << 8) + k0 + lc);
        float2 x2 = *(const float2*)(Wx + ((n0 + lr) << 8) + k0 + lc);
        float2 z2 = *(const float2*)(Wz + ((n0 + lr) << 8) + k0 + lc);
        As [lc][lr] = a2.x; As [lc + 1][lr] = a2.y;
        Bxs[lc][lr] = x2.x; Bxs[lc + 1][lr] = x2.y;
        Bzs[lc][lr] = z2.x; Bzs[lc + 1][lr] = z2.y;
        __syncthreads();
#pragma unroll
        for (int kk = 0; kk < 8; kk++) {
            float ar[4], bx[4], bz[4];
#pragma unroll
            for (int i = 0; i < 4; i++) ar[i] = As[kk][tm + i];
#pragma unroll
            for (int j = 0; j < 4; j++) { bx[j] = Bxs[kk][tn + j]; bz[j] = Bzs[kk][tn + j]; }
#pragma unroll
            for (int i = 0; i < 4; i++)
#pragma unroll
                for (int j = 0; j < 4; j++) {
                    accx[i][j] += ar[i] * bx[j];
                    accz[i][j] += ar[i] * bz[j];
                }
        }
        __syncthreads();
    }

#pragma unroll
    for (int i = 0; i < 4; i++)
#pragma unroll
        for (int j = 0; j < 4; j++) {
            int idx = ((m0 + tm + i) << 8) + n0 + tn + j;
            g_EWx[idx] = accx[i][j];
            g_EG [idx] = 1.0f / (1.0f + __expf(-accz[i][j]));
        }
}

// ---------------------------------------------------------------------------
// Kernel 2: recurrence. Cluster of 2 CTAs per batch; all weights in registers;
// packed f32x2 FMA; per-step h exchange via st.shared::cluster + mbarriers.
// ---------------------------------------------------------------------------
__device__ __forceinline__ void mbar_wait_cluster(uint32_t addr, int parity) {
    asm volatile(
        "{\n\t"
        ".reg .pred P;\n"
        "W1_%=:\n\t"
        "mbarrier.try_wait.parity.acquire.cluster.shared::cta.b64 P, [%0], %1, 0x989680;\n\t"
        "@P bra W2_%=;\n\t"
        "bra W1_%=;\n"
        "W2_%=:\n\t"
        "}" :: "r"(addr), "r"(parity) : "memory");
}

__global__ __launch_bounds__(256, 1) __cluster_dims__(2, 1, 1)
void rnn_recurrence(const int* __restrict__ tokens,
                    const float* __restrict__ Wh) {
    __shared__ float hbuf[2][256];
    __shared__ __align__(8) ull mb[2];
    __shared__ int toks[T + 1];

    uint32_t crank;
    asm("mov.u32 %0, %%cluster_ctarank;" : "=r"(crank));
    const int b    = blockIdx.x >> 1;
    const int tid  = threadIdx.x;
    const int p    = tid >> 1;
    const int half = tid & 1;
    const int d    = (int)(crank << 7) + p;
    const uint32_t peer = crank ^ 1;

    const int* trow = tokens + b * T;
    for (int i = tid; i < T; i += 256) toks[i] = trow[i];
    if (tid == 0) toks[T] = 0;

    hbuf[0][tid] = 0.0f;
    hbuf[1][tid] = 0.0f;

    uint32_t mb_addr0 = (uint32_t)__cvta_generic_to_shared(&mb[0]);
    uint32_t mb_addr1 = (uint32_t)__cvta_generic_to_shared(&mb[1]);
    uint32_t hb_base  = (uint32_t)__cvta_generic_to_shared(&hbuf[0][0]);

    if (tid == 0) {
        asm volatile("mbarrier.init.shared.b64 [%0], 2;" :: "r"(mb_addr0) : "memory");
        asm volatile("mbarrier.init.shared.b64 [%0], 2;" :: "r"(mb_addr1) : "memory");
    }
    __syncthreads();
    asm volatile("barrier.cluster.arrive.aligned;" ::: "memory");
    asm volatile("barrier.cluster.wait.aligned;"   ::: "memory");

    // 128 weight floats in registers as 64 packed f32x2
    ull w[64];
    {
        const ulonglong2* wp = (const ulonglong2*)(Wh + (d << 8) + (half << 7));
#pragma unroll
        for (int q = 0; q < 32; q++) {
            ulonglong2 v = wp[q];
            w[2 * q]     = v.x;
            w[2 * q + 1] = v.y;
        }
    }

    int ph0 = 0, ph1 = 0;
    float wx = 0.0f, g = 0.0f;
    if (!half) {
        int tk = toks[0];
        wx = g_EWx[(tk << 8) + d];
        g  = g_EG [(tk << 8) + d];
    }
    float* outp = g_out + (size_t)b * T * D + d;

    for (int t = 0; t < T; t++) {
        const int buf = t & 1;
        const int nxt = buf ^ 1;

        // prefetch next step's table rows before blocking
        float wxn = 0.0f, gn = 0.0f;
        if (!half) {
            int tk = toks[t + 1];
            wxn = g_EWx[(tk << 8) + d];
            gn  = g_EG [(tk << 8) + d];
        }

        if (t > 0) {
            if (buf == 0) { mbar_wait_cluster(mb_addr0, ph0); ph0 ^= 1; }
            else          { mbar_wait_cluster(mb_addr1, ph1); ph1 ^= 1; }
        }

        const ulonglong2* hp = (const ulonglong2*)(&hbuf[buf][half << 7]);
        ull a0 = 0, a1 = 0, a2 = 0, a3 = 0, a4 = 0, a5 = 0, a6 = 0, a7 = 0;
#pragma unroll
        for (int q = 0; q < 8; q++) {
            ulonglong2 h0 = hp[4 * q + 0];
            ulonglong2 h1 = hp[4 * q + 1];
            ulonglong2 h2 = hp[4 * q + 2];
            ulonglong2 h3 = hp[4 * q + 3];
            a0 = f2fma(w[8 * q + 0], h0.x, a0);
            a1 = f2fma(w[8 * q + 1], h0.y, a1);
            a2 = f2fma(w[8 * q + 2], h1.x, a2);
            a3 = f2fma(w[8 * q + 3], h1.y, a3);
            a4 = f2fma(w[8 * q + 4], h2.x, a4);
            a5 = f2fma(w[8 * q + 5], h2.y, a5);
            a6 = f2fma(w[8 * q + 6], h3.x, a6);
            a7 = f2fma(w[8 * q + 7], h3.y, a7);
        }
        a0 = f2add(a0, a1); a2 = f2add(a2, a3);
        a4 = f2add(a4, a5); a6 = f2add(a6, a7);
        a0 = f2add(a0, a2); a4 = f2add(a4, a6);
        a0 = f2add(a0, a4);
        float s = f2sum(a0);
        s += __shfl_xor_sync(0xffffffffu, s, 1);

        if (!half) {
            float a  = s + wx;
            float e  = __expf(2.0f * a);
            float hn = 1.0f - __fdividef(2.0f, e + 1.0f);
            outp[(size_t)t * D] = hn * g;
            hbuf[nxt][d] = hn;
            uint32_t la = hb_base + (uint32_t)(((nxt << 8) + d) << 2);
            uint32_t ra;
            asm("mapa.shared::cluster.u32 %0, %1, %2;" : "=r"(ra) : "r"(la), "r"(peer));
            asm volatile("st.shared::cluster.f32 [%0], %1;" :: "r"(ra), "f"(hn) : "memory");
        }
        __syncthreads();
        if (tid == 0) {
            asm volatile("mbarrier.arrive.release.cluster.shared::cta.b64 _, [%0];"
                         :: "r"(nxt ? mb_addr1 : mb_addr0) : "memory");
            uint32_t ra;
            asm("mapa.shared::cluster.u32 %0, %1, %2;"
                : "=r"(ra) : "r"(nxt ? mb_addr1 : mb_addr0), "r"(peer));
            asm volatile("mbarrier.arrive.release.cluster.shared::cluster.b64 _, [%0];"
                         :: "r"(ra) : "memory");
        }
        wx = wxn;
        g  = gn;
    }

    asm volatile("barrier.cluster.arrive.aligned;" ::: "memory");
    asm volatile("barrier.cluster.wait.aligned;"   ::: "memory");
}

// ---------------------------------------------------------------------------
// Kernel 3: logits = out @ E^T with packed f32x2 FMA (128x128x8 tiles).
// ---------------------------------------------------------------------------
__global__ __launch_bounds__(256)
void logits_gemm(const float* __restrict__ E, float* __restrict__ C) {
    __shared__ float As[8][128];
    __shared__ float Bs[8][128];

    const float* A = g_out;
    const int m0 = blockIdx.x << 7;
    const int v0 = blockIdx.y << 7;
    const int tid = threadIdx.x;

    const int lr = tid >> 1;
    const int lc = (tid & 1) << 2;
    const int tm = (tid >> 4) << 3;
    const int tv = (tid & 15) << 3;

    ull acc[8][4];
#pragma unroll
    for (int i = 0; i < 8; i++)
#pragma unroll
        for (int j = 0; j < 4; j++) acc[i][j] = 0ull;

    const float* Ag = A + (size_t)(m0 + lr) * D + lc;
    const float* Bg = E + ((v0 + lr) << 8) + lc;

    float4 a4 = *(const float4*)(Ag);
    float4 b4 = *(const float4*)(Bg);

    for (int k0 = 0; k0 < D; k0 += 8) {
        As[lc + 0][lr] = a4.x; As[lc + 1][lr] = a4.y;
        As[lc + 2][lr] = a4.z; As[lc + 3][lr] = a4.w;
        Bs[lc + 0][lr] = b4.x; Bs[lc + 1][lr] = b4.y;
        Bs[lc + 2][lr] = b4.z; Bs[lc + 3][lr] = b4.w;
        __syncthreads();
        if (k0 + 8 < D) {
            a4 = *(const float4*)(Ag + k0 + 8);
            b4 = *(const float4*)(Bg + k0 + 8);
        }
#pragma unroll
        for (int kk = 0; kk < 8; kk++) {
            float ar[8];
#pragma unroll
            for (int i = 0; i < 8; i++) ar[i] = As[kk][tm + i];
            const ull* bp = (const ull*)&Bs[kk][tv];
            ull br0 = bp[0], br1 = bp[1], br2 = bp[2], br3 = bp[3];
#pragma unroll
            for (int i = 0; i < 8; i++) {
                ull ad = f2dup(ar[i]);
                acc[i][0] = f2fma(ad, br0, acc[i][0]);
                acc[i][1] = f2fma(ad, br1, acc[i][1]);
                acc[i][2] = f2fma(ad, br2, acc[i][2]);
                acc[i][3] = f2fma(ad, br3, acc[i][3]);
            }
        }
        __syncthreads();
    }

#pragma unroll
    for (int i = 0; i < 8; i++) {
        float* Cp = C + (size_t)(m0 + tm + i) * V + v0 + tv;
        ((ulonglong2*)Cp)[0] = make_ulonglong2(acc[i][0], acc[i][1]);
        ((ulonglong2*)Cp)[1] = make_ulonglong2(acc[i][2], acc[i][3]);
    }
}

// ---------------------------------------------------------------------------
extern "C" void kernel_launch(void* const* d_in, const int* in_sizes, int n_in,
                              void* d_out, int out_size) {
    const int*   tokens = (const int*)  d_in[0];
    const float* E      = (const float*)d_in[1];
    const float* Wx     = (const float*)d_in[2];
    const float* Wh     = (const float*)d_in[3];
    const float* Wz     = (const float*)d_in[4];
    float* logits = (float*)d_out;

    dim3 pgrid(4, 4);
    precompute_tables<<<pgrid, 256>>>(E, Wx, Wz);

    rnn_recurrence<<<2 * B, 256>>>(tokens, Wh);

    dim3 ggrid((B * T) / 128, V / 128);
    logits_gemm<<<ggrid, 256>>>(E, logits);
}

// round 9
// speedup vs baseline: 1.5284x; 1.5284x over previous
#include <cuda_runtime.h>
#include <cuda_bf16.h>
#include <math.h>
#include <stdint.h>

// Problem constants
#define B   64
#define T   2048
#define D   256
#define V   256

#define GRID_CTAS 148               // one wave, 1 CTA/SM (reg+smem bound)
#define GEMM_CTAS (GRID_CTAS - B)   // 84
#define RWC 192                     // Wh columns held in registers (96 x f32x2)
#define SWC 64                      // Wh columns held in SMEM
#define SSTR 68                     // padded SMEM row stride (floats), 272B = 17*16B
#define CHUNK 128                   // gemm consumes T in chunks of 128 rows

typedef unsigned long long ull;

// Scratch in device globals (no allocations allowed)
__device__ float g_EWx[V * D];              // E @ Wx^T
__device__ float g_EG [V * D];              // sigmoid(E @ Wz^T)
__device__ float g_out[(size_t)B * T * D];  // h_t * gate_t (134 MB)
__device__ int   g_prog[B];                 // per-batch progress (t+1), reset each run

// ---------------------------------------------------------------------------
// f32x2 packed helpers (sm_103a)
// ---------------------------------------------------------------------------
__device__ __forceinline__ ull f2fma(ull a, ull b, ull c) {
    ull d;
    asm("fma.rn.f32x2 %0, %1, %2, %3;" : "=l"(d) : "l"(a), "l"(b), "l"(c));
    return d;
}
__device__ __forceinline__ ull f2add(ull a, ull b) {
    ull d;
    asm("add.rn.f32x2 %0, %1, %2;" : "=l"(d) : "l"(a), "l"(b));
    return d;
}
__device__ __forceinline__ ull f2dup(float x) {
    ull d;
    asm("mov.b64 %0, {%1, %1};" : "=l"(d) : "f"(x));
    return d;
}
__device__ __forceinline__ float f2sum(ull a) {
    float lo, hi;
    asm("mov.b64 {%0, %1}, %2;" : "=f"(lo), "=f"(hi) : "l"(a));
    return lo + hi;
}

// ---------------------------------------------------------------------------
// Kernel 1: precompute token tables as a coalesced dual GEMM (64x64 tiles).
// Also resets g_prog (runs before the fused kernel on the same stream).
// ---------------------------------------------------------------------------
__global__ __launch_bounds__(256)
void precompute_tables(const float* __restrict__ E,
                       const float* __restrict__ Wx,
                       const float* __restrict__ Wz) {
    __shared__ float As[8][64], Bxs[8][64], Bzs[8][64];
    const int m0 = blockIdx.x << 6;
    const int n0 = blockIdx.y << 6;
    const int tid = threadIdx.x;

    if (blockIdx.x == 0 && blockIdx.y == 0 && tid < B) g_prog[tid] = 0;

    const int lr = tid >> 2;
    const int lc = (tid & 3) << 1;
    const int tm = (tid >> 4) << 2;
    const int tn = (tid & 15) << 2;

    float accx[4][4] = {}, accz[4][4] = {};

    for (int k0 = 0; k0 < D; k0 += 8) {
        float2 a2 = *(const float2*)(E  + ((m0 + lr) << 8) + k0 + lc);
        float2 x2 = *(const float2*)(Wx + ((n0 + lr) << 8) + k0 + lc);
        float2 z2 = *(const float2*)(Wz + ((n0 + lr) << 8) + k0 + lc);
        As [lc][lr] = a2.x; As [lc + 1][lr] = a2.y;
        Bxs[lc][lr] = x2.x; Bxs[lc + 1][lr] = x2.y;
        Bzs[lc][lr] = z2.x; Bzs[lc + 1][lr] = z2.y;
        __syncthreads();
#pragma unroll
        for (int kk = 0; kk < 8; kk++) {
            float ar[4], bx[4], bz[4];
#pragma unroll
            for (int i = 0; i < 4; i++) ar[i] = As[kk][tm + i];
#pragma unroll
            for (int j = 0; j < 4; j++) { bx[j] = Bxs[kk][tn + j]; bz[j] = Bzs[kk][tn + j]; }
#pragma unroll
            for (int i = 0; i < 4; i++)
#pragma unroll
                for (int j = 0; j < 4; j++) {
                    accx[i][j] += ar[i] * bx[j];
                    accz[i][j] += ar[i] * bz[j];
                }
        }
        __syncthreads();
    }

#pragma unroll
    for (int i = 0; i < 4; i++)
#pragma unroll
        for (int j = 0; j < 4; j++) {
            int idx = ((m0 + tm + i) << 8) + n0 + tn + j;
            g_EWx[idx] = accx[i][j];
            g_EG [idx] = 1.0f / (1.0f + __expf(-accz[i][j]));
        }
}

// ---------------------------------------------------------------------------
// Kernel 2 (fused): CTAs [0,64) run the recurrence (one batch chain each,
// 192 weight cols in regs + 64 in SMEM, f32x2 FMA). CTAs [64,148) run the
// logits GEMM, consuming 128-row chunks as producers publish them.
// One wave, 1 CTA/SM -> producers always resident -> no deadlock.
// ---------------------------------------------------------------------------
#define FUSED_SMEM_BYTES 81920

__global__ __launch_bounds__(256, 1)
void fused_rnn_gemm(const int*   __restrict__ tokens,
                    const float* __restrict__ Wh,
                    const float* __restrict__ E,
                    float*       __restrict__ C) {
    extern __shared__ __align__(16) float smx[];
    const int cid = blockIdx.x;
    const int tid = threadIdx.x;

    if (cid < B) {
        // ================= recurrence producer =================
        float* Wsm = smx;                      // 256 * SSTR
        float* hb  = smx + 256 * SSTR;         // 2 * 256 (double buffer)
        int*   toks = (int*)(smx + 256 * SSTR + 512);  // T + 1

        const int b = cid;
        const int d = tid;

        const int* trow = tokens + b * T;
        for (int i = tid; i < T; i += 256) toks[i] = trow[i];
        if (tid == 0) toks[T] = 0;

        for (int idx = tid; idx < 256 * SWC; idx += 256) {
            int r = idx >> 6;
            int c = idx & (SWC - 1);
            Wsm[r * SSTR + c] = Wh[(r << 8) + RWC + c];
        }

        // 192 weight floats in registers as 96 packed f32x2
        ull w[96];
        {
            const ulonglong2* wp = (const ulonglong2*)(Wh + (d << 8));
#pragma unroll
            for (int q = 0; q < 48; q++) {
                ulonglong2 v = wp[q];
                w[2 * q]     = v.x;
                w[2 * q + 1] = v.y;
            }
        }

        hb[tid] = 0.0f;
        hb[256 + tid] = 0.0f;
        __syncthreads();

        int tk0 = toks[0];
        float wx = g_EWx[(tk0 << 8) + d];
        float g  = g_EG [(tk0 << 8) + d];

        float* outp = g_out + (size_t)b * T * D + d;
        const ulonglong2* wsp = (const ulonglong2*)(Wsm + d * SSTR);

        for (int t = 0; t < T; t++) {
            const int buf = t & 1;

            // prefetch next step's table rows (hidden under FMAs)
            int tkn = toks[t + 1];
            float wxn = g_EWx[(tkn << 8) + d];
            float gn  = g_EG [(tkn << 8) + d];

            const ulonglong2* hp = (const ulonglong2*)(hb + (buf << 8));
            ull a0 = 0, a1 = 0, a2 = 0, a3 = 0, a4 = 0, a5 = 0, a6 = 0, a7 = 0;

            // register-weight part: k in [0,192)
#pragma unroll
            for (int q = 0; q < 12; q++) {
                ulonglong2 h0 = hp[4 * q + 0];
                ulonglong2 h1 = hp[4 * q + 1];
                ulonglong2 h2 = hp[4 * q + 2];
                ulonglong2 h3 = hp[4 * q + 3];
                a0 = f2fma(w[8 * q + 0], h0.x, a0);
                a1 = f2fma(w[8 * q + 1], h0.y, a1);
                a2 = f2fma(w[8 * q + 2], h1.x, a2);
                a3 = f2fma(w[8 * q + 3], h1.y, a3);
                a4 = f2fma(w[8 * q + 4], h2.x, a4);
                a5 = f2fma(w[8 * q + 5], h2.y, a5);
                a6 = f2fma(w[8 * q + 6], h3.x, a6);
                a7 = f2fma(w[8 * q + 7], h3.y, a7);
            }
            // smem-weight part: k in [192,256)
#pragma unroll
            for (int q = 0; q < 4; q++) {
                ulonglong2 h0 = hp[48 + 4 * q + 0];
                ulonglong2 h1 = hp[48 + 4 * q + 1];
                ulonglong2 h2 = hp[48 + 4 * q + 2];
                ulonglong2 h3 = hp[48 + 4 * q + 3];
                ulonglong2 w0 = wsp[4 * q + 0];
                ulonglong2 w1 = wsp[4 * q + 1];
                ulonglong2 w2 = wsp[4 * q + 2];
                ulonglong2 w3 = wsp[4 * q + 3];
                a0 = f2fma(w0.x, h0.x, a0);
                a1 = f2fma(w0.y, h0.y, a1);
                a2 = f2fma(w1.x, h1.x, a2);
                a3 = f2fma(w1.y, h1.y, a3);
                a4 = f2fma(w2.x, h2.x, a4);
                a5 = f2fma(w2.y, h2.y, a5);
                a6 = f2fma(w3.x, h3.x, a6);
                a7 = f2fma(w3.y, h3.y, a7);
            }

            a0 = f2add(a0, a1); a2 = f2add(a2, a3);
            a4 = f2add(a4, a5); a6 = f2add(a6, a7);
            a0 = f2add(a0, a2); a4 = f2add(a4, a6);
            a0 = f2add(a0, a4);
            float s = f2sum(a0) + wx;

            float e  = __expf(2.0f * s);
            float hn = 1.0f - __fdividef(2.0f, e + 1.0f);

            outp[(size_t)t * D] = hn * g;
            hb[((buf ^ 1) << 8) + d] = hn;
            __syncthreads();

            // publish progress every 64 steps (release)
            if (((t & 63) == 63) && tid == 0) {
                __threadfence();
                *(volatile int*)&g_prog[b] = t + 1;
            }
            wx = wxn;
            g  = gn;
        }
    } else {
        // ================= logits GEMM consumer =================
        float* As = smx;           // [8][128]
        float* Bs = smx + 1024;    // [8][128]

        const int lr = tid >> 1;
        const int lc = (tid & 1) << 2;
        const int tm = (tid >> 4) << 3;
        const int tv = (tid & 15) << 3;

        const int njobs = B * (T / CHUNK) * (V / 128);   // 2048

        for (int j = cid - B; j < njobs; j += GEMM_CTAS) {
            const int tc  = j >> 7;          // chunk index (t-major => producers ahead)
            const int rem = j & 127;
            const int bb  = rem >> 1;
            const int vt  = rem & 1;

            // acquire: wait until batch bb has produced chunk tc
            if (tid == 0) {
                const int need = (tc + 1) * CHUNK;
                unsigned ns = 64;
                while (*(volatile int*)&g_prog[bb] < need) {
                    __nanosleep(ns);
                    if (ns < 1024) ns <<= 1;
                }
                __threadfence();
            }
            __syncthreads();

            const size_t m0 = (size_t)bb * T + (size_t)tc * CHUNK;
            const int v0 = vt << 7;

            ull acc[8][4];
#pragma unroll
            for (int i = 0; i < 8; i++)
#pragma unroll
                for (int jj = 0; jj < 4; jj++) acc[i][jj] = 0ull;

            const float* Ag = g_out + (m0 + lr) * D + lc;
            const float* Bg = E + ((v0 + lr) << 8) + lc;

            float4 a4 = *(const float4*)(Ag);
            float4 b4 = *(const float4*)(Bg);

            for (int k0 = 0; k0 < D; k0 += 8) {
                As[(lc + 0) * 128 + lr] = a4.x; As[(lc + 1) * 128 + lr] = a4.y;
                As[(lc + 2) * 128 + lr] = a4.z; As[(lc + 3) * 128 + lr] = a4.w;
                Bs[(lc + 0) * 128 + lr] = b4.x; Bs[(lc + 1) * 128 + lr] = b4.y;
                Bs[(lc + 2) * 128 + lr] = b4.z; Bs[(lc + 3) * 128 + lr] = b4.w;
                __syncthreads();
                if (k0 + 8 < D) {
                    a4 = *(const float4*)(Ag + k0 + 8);
                    b4 = *(const float4*)(Bg + k0 + 8);
                }
#pragma unroll
                for (int kk = 0; kk < 8; kk++) {
                    float ar[8];
#pragma unroll
                    for (int i = 0; i < 8; i++) ar[i] = As[kk * 128 + tm + i];
                    const ull* bp = (const ull*)&Bs[kk * 128 + tv];
                    ull br0 = bp[0], br1 = bp[1], br2 = bp[2], br3 = bp[3];
#pragma unroll
                    for (int i = 0; i < 8; i++) {
                        ull ad = f2dup(ar[i]);
                        acc[i][0] = f2fma(ad, br0, acc[i][0]);
                        acc[i][1] = f2fma(ad, br1, acc[i][1]);
                        acc[i][2] = f2fma(ad, br2, acc[i][2]);
                        acc[i][3] = f2fma(ad, br3, acc[i][3]);
                    }
                }
                __syncthreads();
            }

#pragma unroll
            for (int i = 0; i < 8; i++) {
                float* Cp = C + (m0 + tm + i) * V + v0 + tv;
                ((ulonglong2*)Cp)[0] = make_ulonglong2(acc[i][0], acc[i][1]);
                ((ulonglong2*)Cp)[1] = make_ulonglong2(acc[i][2], acc[i][3]);
            }
        }
    }
}

// ---------------------------------------------------------------------------
extern "C" void kernel_launch(void* const* d_in, const int* in_sizes, int n_in,
                              void* d_out, int out_size) {
    const int*   tokens = (const int*)  d_in[0];
    const float* E      = (const float*)d_in[1];
    const float* Wx     = (const float*)d_in[2];
    const float* Wh     = (const float*)d_in[3];
    const float* Wz     = (const float*)d_in[4];
    float* logits = (float*)d_out;

    dim3 pgrid(4, 4);
    precompute_tables<<<pgrid, 256>>>(E, Wx, Wz);

    cudaFuncSetAttribute(fused_rnn_gemm,
                         cudaFuncAttributeMaxDynamicSharedMemorySize,
                         FUSED_SMEM_BYTES);
    fused_rnn_gemm<<<GRID_CTAS, 256, FUSED_SMEM_BYTES>>>(tokens, Wh, E, logits);
}